// round 1
// baseline (speedup 1.0000x reference)
#include <cuda_runtime.h>

#define BB 4
#define CC 64
#define C8 8
#define NN 9216          // 96*96
#define TN 128           // query tile per block
#define TM 64            // key/value chunk
#define SROW 66          // padded smem row stride (floats) for 64-wide tiles

typedef unsigned long long u64;

// ---------------- scratch (no allocs allowed) ----------------
__device__ float g_Q[BB * C8 * NN];              // [b][k][n]
__device__ float g_K[BB * C8 * NN];              // [b][k][n]
__device__ float g_Vt[(size_t)BB * NN * CC];     // [b][n][c]  (transposed V)
__device__ float g_avg[BB * CC];
__device__ float g_mx[BB * CC];
__device__ float g_scale[BB * CC];

// ---------------- f32x2 helpers (FFMA2 path) ----------------
__device__ __forceinline__ u64 f2_fma(u64 a, u64 b, u64 c) {
    u64 d;
    asm("fma.rn.f32x2 %0, %1, %2, %3;" : "=l"(d) : "l"(a), "l"(b), "l"(c));
    return d;
}
__device__ __forceinline__ u64 f2_pack(float lo, float hi) {
    u64 d; asm("mov.b64 %0, {%1, %2};" : "=l"(d) : "f"(lo), "f"(hi)); return d;
}
__device__ __forceinline__ void f2_unpack(u64 v, float &lo, float &hi) {
    asm("mov.b64 {%0, %1}, %2;" : "=f"(lo), "=f"(hi) : "l"(v));
}
__device__ __forceinline__ float sigm(float x) {
    return __fdividef(1.0f, 1.0f + __expf(-x));
}

// ---------------- kernel 1: fused 1x1-conv Q/K/V ----------------
__global__ __launch_bounds__(256) void qkv_kernel(
    const float* __restrict__ x,
    const float* __restrict__ wq, const float* __restrict__ bq,
    const float* __restrict__ wk, const float* __restrict__ bk,
    const float* __restrict__ wv, const float* __restrict__ bv)
{
    __shared__ float sw[80 * 64];  // rows 0..7 wq, 8..15 wk, 16..79 wv
    __shared__ float sb[80];
    int tid = threadIdx.x;
    for (int i = tid; i < 512;  i += 256) sw[i] = wq[i];
    for (int i = tid; i < 512;  i += 256) sw[512 + i] = wk[i];
    for (int i = tid; i < 4096; i += 256) sw[1024 + i] = wv[i];
    if (tid < 80) sb[tid] = (tid < 8) ? bq[tid] : (tid < 16 ? bk[tid - 8] : bv[tid - 16]);
    __syncthreads();

    int n = blockIdx.x * 256 + tid;
    int b = blockIdx.y;
    const float* xb = x + (size_t)b * CC * NN + n;
    float xr[CC];
    #pragma unroll
    for (int c = 0; c < CC; c++) xr[c] = xb[(size_t)c * NN];

    #pragma unroll 1
    for (int o = 0; o < C8; o++) {
        float aq = sb[o], ak = sb[8 + o];
        const float* wqr = sw + o * 64;
        const float* wkr = sw + 512 + o * 64;
        #pragma unroll
        for (int c = 0; c < CC; c++) { aq += wqr[c] * xr[c]; ak += wkr[c] * xr[c]; }
        g_Q[((size_t)b * C8 + o) * NN + n] = aq;
        g_K[((size_t)b * C8 + o) * NN + n] = ak;
    }
    float* vrow = g_Vt + ((size_t)b * NN + n) * CC;
    #pragma unroll 1
    for (int o = 0; o < CC; o++) {
        float av = sb[16 + o];
        const float* wvr = sw + 1024 + o * 64;
        #pragma unroll
        for (int c = 0; c < CC; c++) av += wvr[c] * xr[c];
        vrow[o] = av;
    }
}

// ---------------- kernel 2: fused sigmoid-attention, flash style ----------------
// block: 128 queries x 64 channels output tile; loop over 144 key chunks of 64.
// SMEM layouts chosen so the hot loop's f32x2 loads are natural m-pairs:
//   Vs[c][m] (stride 66), As[n][m] (stride 66) -> LDS.64 conflict-free w/ broadcast.
__global__ __launch_bounds__(256, 2) void attn_kernel(
    const float* __restrict__ x, float* __restrict__ out)
{
    extern __shared__ float sh[];
    float* Qs = sh;                    // [8][128]
    float* Ks = Qs + C8 * TN;          // [8][SROW]
    float* Vs = Ks + C8 * SROW;        // [64][SROW]
    float* As = Vs + CC * SROW;        // [128][SROW]

    int tid = threadIdx.x;
    int b  = blockIdx.y;
    int n0 = blockIdx.x * TN;

    for (int i = tid; i < C8 * TN; i += 256) {
        int kk = i >> 7, nn = i & 127;
        Qs[i] = g_Q[((size_t)b * C8 + kk) * NN + n0 + nn];
    }

    u64 acc[8][4];   // [c-sub][n-sub], each packed over (m even, m odd)
    #pragma unroll
    for (int i = 0; i < 8; i++)
        #pragma unroll
        for (int j = 0; j < 4; j++) acc[i][j] = 0ULL;

    const int cgrp  = tid & 7;          // c = cgrp + 8*i  (interleaved -> no LDS conflicts)
    const int ngrp  = tid >> 3;         // n = n0 + ngrp*4 + j
    const int na    = tid & 127;        // score row this thread computes
    const int mbase = (tid >> 7) * 32;  // score m-range base (2 groups of 32)

    for (int m0 = 0; m0 < NN; m0 += TM) {
        __syncthreads();
        for (int i = tid; i < C8 * TM; i += 256) {
            int kk = i >> 6, mm = i & 63;
            Ks[kk * SROW + mm] = g_K[((size_t)b * C8 + kk) * NN + m0 + mm];
        }
        for (int i = tid; i < CC * TM; i += 256) {
            int mm = i >> 6, cc = i & 63;
            Vs[cc * SROW + mm] = g_Vt[((size_t)b * NN + m0 + mm) * CC + cc];
        }
        __syncthreads();

        // scores: att[na][mbase..mbase+31] = sigmoid(sum_k Q[k][na]*K[k][m])
        #pragma unroll 1
        for (int half = 0; half < 2; half++) {
            u64 e[8];
            #pragma unroll
            for (int p = 0; p < 8; p++) e[p] = 0ULL;
            #pragma unroll
            for (int k = 0; k < C8; k++) {
                float qv = Qs[k * TN + na];
                u64 q2 = f2_pack(qv, qv);
                const u64* krow = (const u64*)(Ks + k * SROW + mbase + half * 16);
                #pragma unroll
                for (int p = 0; p < 8; p++) e[p] = f2_fma(q2, krow[p], e[p]);
            }
            u64* arow = (u64*)(As + na * SROW + mbase + half * 16);
            #pragma unroll
            for (int p = 0; p < 8; p++) {
                float lo, hi; f2_unpack(e[p], lo, hi);
                arow[p] = f2_pack(sigm(lo), sigm(hi));
            }
        }
        __syncthreads();

        // main accumulate: acc[c][n] += V[c][m] * att[n][m], packed over m-pairs
        const u64* a0 = (const u64*)(As + (ngrp * 4 + 0) * SROW);
        const u64* a1 = (const u64*)(As + (ngrp * 4 + 1) * SROW);
        const u64* a2 = (const u64*)(As + (ngrp * 4 + 2) * SROW);
        const u64* a3 = (const u64*)(As + (ngrp * 4 + 3) * SROW);
        #pragma unroll 2
        for (int mp = 0; mp < TM / 2; mp++) {
            u64 av0 = a0[mp], av1 = a1[mp], av2 = a2[mp], av3 = a3[mp];
            #pragma unroll
            for (int i = 0; i < 8; i++) {
                u64 v = *(const u64*)(Vs + (cgrp + 8 * i) * SROW + 2 * mp);
                acc[i][0] = f2_fma(v, av0, acc[i][0]);
                acc[i][1] = f2_fma(v, av1, acc[i][1]);
                acc[i][2] = f2_fma(v, av2, acc[i][2]);
                acc[i][3] = f2_fma(v, av3, acc[i][3]);
            }
        }
    }

    // epilogue: horizontal add of m-pairs, residual, vectorized store
    #pragma unroll
    for (int i = 0; i < 8; i++) {
        int c = cgrp + 8 * i;
        size_t base = ((size_t)b * CC + c) * NN + n0 + ngrp * 4;
        float4 xv = *(const float4*)(x + base);
        float r[4];
        #pragma unroll
        for (int j = 0; j < 4; j++) {
            float lo, hi; f2_unpack(acc[i][j], lo, hi);
            r[j] = lo + hi;
        }
        *(float4*)(out + base) = make_float4(r[0] + xv.x, r[1] + xv.y,
                                             r[2] + xv.z, r[3] + xv.w);
    }
}

// ---------------- kernel 3: per-(b,c) mean & max over N ----------------
__global__ __launch_bounds__(256) void reduce_kernel(const float* __restrict__ out)
{
    __shared__ float ss[256], sm[256];
    int c = blockIdx.x, b = blockIdx.y;
    const float* row = out + ((size_t)b * CC + c) * NN;
    float s = 0.f, m = -3.4e38f;
    for (int i = threadIdx.x; i < NN; i += 256) {
        float v = row[i]; s += v; m = fmaxf(m, v);
    }
    ss[threadIdx.x] = s; sm[threadIdx.x] = m;
    __syncthreads();
    for (int o = 128; o > 0; o >>= 1) {
        if (threadIdx.x < o) {
            ss[threadIdx.x] += ss[threadIdx.x + o];
            sm[threadIdx.x] = fmaxf(sm[threadIdx.x], sm[threadIdx.x + o]);
        }
        __syncthreads();
    }
    if (threadIdx.x == 0) {
        g_avg[b * CC + c] = ss[0] * (1.0f / NN);
        g_mx[b * CC + c]  = sm[0];
    }
}

// ---------------- kernel 4: CBAM MLP -> sigmoid scale ----------------
__global__ __launch_bounds__(256) void scale_kernel(
    const float* __restrict__ w1, const float* __restrict__ w2)
{
    __shared__ float sa[256], sm[256], s1[256], s2[256];
    int tid = threadIdx.x;
    sa[tid] = g_avg[tid]; sm[tid] = g_mx[tid]; s1[tid] = w1[tid]; s2[tid] = w2[tid];
    __syncthreads();
    int b = tid >> 6, c = tid & 63;
    float y = 0.f;
    #pragma unroll
    for (int r = 0; r < 4; r++) {
        float ha = 0.f, hm = 0.f;
        #pragma unroll 16
        for (int cc = 0; cc < 64; cc++) {
            float w = s1[r * 64 + cc];
            ha += w * sa[b * 64 + cc];
            hm += w * sm[b * 64 + cc];
        }
        float wv = s2[c * 4 + r];
        y += wv * fmaxf(ha, 0.f) + wv * fmaxf(hm, 0.f);
    }
    g_scale[tid] = 1.0f / (1.0f + expf(-y));
}

// ---------------- kernel 5: apply channel scale in place ----------------
__global__ __launch_bounds__(256) void apply_scale_kernel(float* __restrict__ out)
{
    int idx = blockIdx.x * 256 + threadIdx.x;
    const int total4 = BB * CC * NN / 4;
    if (idx < total4) {
        int bc = (idx * 4) / NN;   // NN % 4 == 0 -> same (b,c) for all 4 lanes
        float s = g_scale[bc];
        float4 v = ((float4*)out)[idx];
        v.x *= s; v.y *= s; v.z *= s; v.w *= s;
        ((float4*)out)[idx] = v;
    }
}

// ---------------- launch ----------------
extern "C" void kernel_launch(void* const* d_in, const int* in_sizes, int n_in,
                              void* d_out, int out_size)
{
    const float* x     = (const float*)d_in[0];
    const float* wq    = (const float*)d_in[1];
    const float* bq    = (const float*)d_in[2];
    const float* wk    = (const float*)d_in[3];
    const float* bk    = (const float*)d_in[4];
    const float* wv    = (const float*)d_in[5];
    const float* bv    = (const float*)d_in[6];
    const float* ca_w1 = (const float*)d_in[7];
    const float* ca_w2 = (const float*)d_in[8];
    float* out = (float*)d_out;

    const int smem_bytes = (C8 * TN + C8 * SROW + CC * SROW + TN * SROW) * 4; // 56896
    cudaFuncSetAttribute(attn_kernel, cudaFuncAttributeMaxDynamicSharedMemorySize, smem_bytes);

    qkv_kernel<<<dim3(NN / 256, BB), 256>>>(x, wq, bq, wk, bk, wv, bv);
    attn_kernel<<<dim3(NN / TN, BB), 256, smem_bytes>>>(x, out);
    reduce_kernel<<<dim3(CC, BB), 256>>>(out);
    scale_kernel<<<1, 256>>>(ca_w1, ca_w2);
    apply_scale_kernel<<<(BB * CC * NN / 4 + 255) / 256, 256>>>(out);
}